// round 1
// baseline (speedup 1.0000x reference)
#include <cuda_runtime.h>

#define N_PTS 100000
#define K_C   512
#define D_DIM 256
#define EPS_M 0.02f

// ---------------- device scratch (no allocations allowed) ----------------
__device__ float g_sums[K_C * D_DIM];   // segment sums
__device__ float g_cnt[K_C];            // segment counts
__device__ float g_upd[K_C * D_DIM];    // updated centroids
__device__ float g_cch1[K_C];           // 0.5*|c|^2 (original)
__device__ float g_cch2[K_C];           // 0.5*|c|^2 (updated)
__device__ int   g_assign1[N_PTS];      // pass-1 argmin (no-update fallback)
__device__ int   g_match;
__device__ int   g_prev64;              // 1 if prev_assignments is int64

// ---------------- helpers ----------------
__device__ __forceinline__ unsigned long long pack2(float lo, float hi) {
    unsigned long long r;
    asm("mov.b64 %0, {%1, %2};" : "=l"(r) : "f"(lo), "f"(hi));
    return r;
}
__device__ __forceinline__ void unpack2(unsigned long long v, float& lo, float& hi) {
    asm("mov.b64 {%0, %1}, %2;" : "=f"(lo), "=f"(hi) : "l"(v));
}
__device__ __forceinline__ unsigned long long ffma2(unsigned long long a,
                                                    unsigned long long b,
                                                    unsigned long long c) {
    unsigned long long d;
    asm("fma.rn.f32x2 %0, %1, %2, %3;" : "=l"(d) : "l"(a), "l"(b), "l"(c));
    return d;
}
__device__ __forceinline__ int get_prev(const void* prev, int i) {
    if (g_prev64) return (int)((const long long*)prev)[i];
    return ((const int*)prev)[i];
}

// ---------------- init: zero accumulators, 0.5|c|^2, dtype detect ----------------
__global__ void __launch_bounds__(256) init_kernel(const float* __restrict__ cents,
                                                   const void* __restrict__ prev) {
    int k = blockIdx.x, tid = threadIdx.x;
    g_sums[k * D_DIM + tid] = 0.0f;
    float v = cents[k * D_DIM + tid];
    float s = v * v;
    #pragma unroll
    for (int off = 16; off > 0; off >>= 1) s += __shfl_down_sync(0xffffffffu, s, off);
    __shared__ float ws[8];
    if ((tid & 31) == 0) ws[tid >> 5] = s;
    __syncthreads();
    if (tid == 0) {
        float tot = 0.0f;
        #pragma unroll
        for (int j = 0; j < 8; j++) tot += ws[j];
        g_cch1[k] = 0.5f * tot;
        g_cnt[k] = 0.0f;
    }
    if (k == 0 && tid == 0) {
        g_match = 1;
        // int64 detection: upper words of first 64 entries all zero
        const int* p32 = (const int*)prev;
        int is64 = 1;
        for (int j = 0; j < 64; j++)
            if (p32[2 * j + 1] != 0) { is64 = 0; break; }
        g_prev64 = is64;
    }
}

// ---------------- scatter: segment sums / counts keyed on prev ----------------
__global__ void __launch_bounds__(256) scatter_kernel(const float* __restrict__ x,
                                                      const void* __restrict__ prev) {
    int gw = (blockIdx.x * blockDim.x + threadIdx.x) >> 5;
    int lane = threadIdx.x & 31;
    if (gw >= N_PTS) return;
    int a = get_prev(prev, gw);
    const float4* xr = (const float4*)(x + (size_t)gw * D_DIM);
    float* dst = g_sums + (size_t)a * D_DIM;
    #pragma unroll
    for (int j = 0; j < 2; j++) {
        float4 v = xr[lane + j * 32];
        asm volatile("red.global.add.v4.f32 [%0], {%1, %2, %3, %4};"
                     :: "l"(dst + (lane + j * 32) * 4),
                        "f"(v.x), "f"(v.y), "f"(v.z), "f"(v.w) : "memory");
    }
    if (lane == 0) atomicAdd(&g_cnt[a], 1.0f);
}

// ---------------- finalize: EMA update + 0.5|c|^2 + centroid/flag output ----------------
__global__ void __launch_bounds__(256) finalize_kernel(const float* __restrict__ cents,
                                                       float* __restrict__ out) {
    int k = blockIdx.x, tid = threadIdx.x;
    int match = g_match;
    float c0 = cents[k * D_DIM + tid];
    float up;
    if (match) up = 0.01f * c0 + 0.99f * (g_sums[k * D_DIM + tid] / g_cnt[k]);
    else       up = c0;
    g_upd[k * D_DIM + tid] = up;
    out[N_PTS + 1 + k * D_DIM + tid] = up;
    float s = up * up;
    #pragma unroll
    for (int off = 16; off > 0; off >>= 1) s += __shfl_down_sync(0xffffffffu, s, off);
    __shared__ float ws[8];
    if ((tid & 31) == 0) ws[tid >> 5] = s;
    __syncthreads();
    if (tid == 0) {
        float tot = 0.0f;
        #pragma unroll
        for (int j = 0; j < 8; j++) tot += ws[j];
        g_cch2[k] = 0.5f * tot;
    }
    if (k == 0 && tid == 0) out[N_PTS] = match ? 1.0f : 0.0f;
}

// ---------------- argmin pass: tiled 64pts x 512k, FFMA2 register blocking --------
// PASS=1: original centroids; writes g_assign1 + match check vs prev.
// PASS=2: updated centroids; writes float assignments to out.
template <int PASS>
__global__ void __launch_bounds__(256) pass_kernel(const float* __restrict__ x,
                                                   const float* __restrict__ cents_in,
                                                   const void* __restrict__ prev,
                                                   float* __restrict__ out) {
    const float* cents = (PASS == 2) ? g_upd : cents_in;
    const float* cch   = (PASS == 2) ? g_cch2 : g_cch1;

    __shared__ __align__(16) float xs[32][68];    // [d][point]
    __shared__ __align__(16) float cs[32][132];   // [d][k]
    __shared__ float cchs[K_C];

    int tid = threadIdx.x;
    int tx = tid & 15;        // k-group: ks tx*8 .. tx*8+7 within chunk
    int ty = tid >> 4;        // point-group: points ty*4 .. ty*4+3
    int i0 = blockIdx.x * 64;

    for (int k = tid; k < K_C; k += 256) cchs[k] = cch[k];

    float bestv[4]; int besti[4]; float mprev[4]; int pv[4];
    #pragma unroll
    for (int p = 0; p < 4; p++) { bestv[p] = -1e30f; besti[p] = 0; mprev[p] = -1e30f; pv[p] = -1; }
    if (PASS == 1) {
        #pragma unroll
        for (int p = 0; p < 4; p++) {
            int i = i0 + ty * 4 + p;
            if (i < N_PTS) pv[p] = get_prev(prev, i);
        }
    }

    for (int kc = 0; kc < 4; kc++) {
        int k0 = kc * 128;
        unsigned long long acc[4][4];
        #pragma unroll
        for (int p = 0; p < 4; p++)
            #pragma unroll
            for (int q = 0; q < 4; q++) acc[p][q] = 0ull;

        for (int dc = 0; dc < D_DIM; dc += 32) {
            __syncthreads();
            // load x tile (transposed): 64 pts x 32 dims = 512 float4
            #pragma unroll
            for (int t = tid; t < 512; t += 256) {
                int il = t >> 3, d4 = (t & 7) * 4;
                int gi = i0 + il; if (gi >= N_PTS) gi = 0;
                float4 v = *(const float4*)(x + (size_t)gi * D_DIM + dc + d4);
                xs[d4 + 0][il] = v.x; xs[d4 + 1][il] = v.y;
                xs[d4 + 2][il] = v.z; xs[d4 + 3][il] = v.w;
            }
            // load c tile (transposed): 128 ks x 32 dims = 1024 float4
            #pragma unroll
            for (int t = tid; t < 1024; t += 256) {
                int kl = t >> 3, d4 = (t & 7) * 4;
                float4 v = *(const float4*)(cents + (size_t)(k0 + kl) * D_DIM + dc + d4);
                cs[d4 + 0][kl] = v.x; cs[d4 + 1][kl] = v.y;
                cs[d4 + 2][kl] = v.z; cs[d4 + 3][kl] = v.w;
            }
            __syncthreads();
            #pragma unroll
            for (int d = 0; d < 32; d++) {
                float4 ca = *(const float4*)&cs[d][tx * 8];
                float4 cb = *(const float4*)&cs[d][tx * 8 + 4];
                unsigned long long cp[4];
                cp[0] = pack2(ca.x, ca.y); cp[1] = pack2(ca.z, ca.w);
                cp[2] = pack2(cb.x, cb.y); cp[3] = pack2(cb.z, cb.w);
                #pragma unroll
                for (int p = 0; p < 4; p++) {
                    float xv = xs[d][ty * 4 + p];
                    unsigned long long xp = pack2(xv, xv);
                    #pragma unroll
                    for (int q = 0; q < 4; q++) acc[p][q] = ffma2(xp, cp[q], acc[p][q]);
                }
            }
        }
        // chunk epilogue: m = dot - 0.5|c|^2, running argmax (ties -> lowest k)
        #pragma unroll
        for (int p = 0; p < 4; p++) {
            #pragma unroll
            for (int q = 0; q < 4; q++) {
                float lo, hi; unpack2(acc[p][q], lo, hi);
                int k_lo = k0 + tx * 8 + q * 2;
                int k_hi = k_lo + 1;
                float mlo = lo - cchs[k_lo];
                float mhi = hi - cchs[k_hi];
                if (mlo > bestv[p]) { bestv[p] = mlo; besti[p] = k_lo; }
                if (mhi > bestv[p]) { bestv[p] = mhi; besti[p] = k_hi; }
                if (PASS == 1) {
                    if (k_lo == pv[p]) mprev[p] = mlo;
                    if (k_hi == pv[p]) mprev[p] = mhi;
                }
            }
        }
    }

    // cross-lane reduce over the 16 tx lanes (half-warp, width=16)
    #pragma unroll
    for (int p = 0; p < 4; p++) {
        float bv = bestv[p]; int bi = besti[p]; float mp = mprev[p];
        #pragma unroll
        for (int off = 8; off > 0; off >>= 1) {
            float ov  = __shfl_down_sync(0xffffffffu, bv, off, 16);
            int   oi  = __shfl_down_sync(0xffffffffu, bi, off, 16);
            float omp = __shfl_down_sync(0xffffffffu, mp, off, 16);
            if (ov > bv || (ov == bv && oi < bi)) { bv = ov; bi = oi; }
            if (omp > mp) mp = omp;
        }
        if (tx == 0) {
            int i = i0 + ty * 4 + p;
            if (i < N_PTS) {
                if (PASS == 1) {
                    g_assign1[i] = bi;
                    if (mp < bv - EPS_M) g_match = 0;
                } else {
                    int a = g_match ? bi : g_assign1[i];
                    out[i] = (float)a;
                }
            }
        }
    }
}

// ---------------- launch ----------------
extern "C" void kernel_launch(void* const* d_in, const int* in_sizes, int n_in,
                              void* d_out, int out_size) {
    const float* x     = (const float*)d_in[0];
    const float* cents = (const float*)d_in[1];
    const void*  prev  = d_in[2];
    float* out = (float*)d_out;

    init_kernel<<<K_C, 256>>>(cents, prev);
    scatter_kernel<<<(N_PTS * 32 + 255) / 256, 256>>>(x, prev);
    pass_kernel<1><<<(N_PTS + 63) / 64, 256>>>(x, cents, prev, out);
    finalize_kernel<<<K_C, 256>>>(cents, out);
    pass_kernel<2><<<(N_PTS + 63) / 64, 256>>>(x, cents, prev, out);
}

// round 3
// speedup vs baseline: 1.8427x; 1.8427x over previous
#include <cuda_runtime.h>
#include <cuda_fp16.h>
#include <cstdint>

#define N_PTS  100000
#define N_PAD  100032          // 1563 * 64
#define K_C    512
#define D_DIM  256
#define KTOT   768
#define KC     64
#define NCH    12
#define MT     64
#define EPS_M  0.02f

// ---------------- device scratch ----------------
__device__ __half g_Xcat[(size_t)N_PAD * KTOT];   // [xh | xh | xl]
__device__ __half g_Bcat1[K_C * KTOT];            // [ch | cl | ch] original
__device__ __half g_Bcat2[K_C * KTOT];            // updated
__device__ float  g_sums[K_C * D_DIM];
__device__ int    g_cnti[K_C];
__device__ int    g_start[K_C];
__device__ int    g_cursor[K_C];
__device__ int    g_idx[N_PTS];
__device__ float  g_cch1[K_C];
__device__ float  g_cch2[K_C];
__device__ int    g_assign1[N_PTS];
__device__ int    g_match;
__device__ int    g_prev64;

// ---------------- helpers ----------------
__device__ __forceinline__ int get_prev(const void* prev, int i) {
    if (g_prev64) return (int)((const long long*)prev)[i];
    return ((const int*)prev)[i];
}
__device__ __forceinline__ uint32_t smem_u32(const void* p) {
    uint32_t a;
    asm("{ .reg .u64 t; cvta.to.shared.u64 t, %1; cvt.u32.u64 %0, t; }" : "=r"(a) : "l"(p));
    return a;
}
__device__ __forceinline__ uint32_t sw128(uint32_t o) { return o ^ ((o >> 3) & 0x70u); }

__device__ __forceinline__ void cpasync16(uint32_t s, const void* g) {
    asm volatile("cp.async.cg.shared.global [%0], [%1], 16;" :: "r"(s), "l"(g));
}
__device__ __forceinline__ void ldsm_x4(uint32_t* r, uint32_t addr) {
    asm volatile("ldmatrix.sync.aligned.m8n8.x4.shared.b16 {%0,%1,%2,%3}, [%4];"
                 : "=r"(r[0]), "=r"(r[1]), "=r"(r[2]), "=r"(r[3]) : "r"(addr));
}
__device__ __forceinline__ void mma16816(float* c, const uint32_t* a, uint32_t b0, uint32_t b1) {
    asm volatile("mma.sync.aligned.m16n8k16.row.col.f32.f16.f16.f32 "
                 "{%0,%1,%2,%3}, {%4,%5,%6,%7}, {%8,%9}, {%0,%1,%2,%3};"
                 : "+f"(c[0]), "+f"(c[1]), "+f"(c[2]), "+f"(c[3])
                 : "r"(a[0]), "r"(a[1]), "r"(a[2]), "r"(a[3]), "r"(b0), "r"(b1));
}

// ---------------- SMEM layout (dynamic) ----------------
#define SA     0               // 2 x 8192
#define SB     16384           // 2 x 65536
#define SCCH   147456          // 2048
#define SRV    149504          // float[256]
#define SRI    150528          // int[256]
#define SRP    151552          // float[256]
#define SM_TOT 152576

// ---------------- xcat: split x into fp16 [xh|xh|xl] ----------------
__global__ void __launch_bounds__(256) xcat_kernel(const float* __restrict__ x) {
    int idx = blockIdx.x * 256 + threadIdx.x;
    int i = idx >> 6, t = idx & 63;
    if (i >= N_PAD) return;
    float4 v = make_float4(0.f, 0.f, 0.f, 0.f);
    if (i < N_PTS) v = *(const float4*)(x + (size_t)i * D_DIM + t * 4);
    __half hx = __float2half_rn(v.x), hy = __float2half_rn(v.y);
    __half hz = __float2half_rn(v.z), hw = __float2half_rn(v.w);
    __half lx = __float2half_rn(v.x - __half2float(hx));
    __half ly = __float2half_rn(v.y - __half2float(hy));
    __half lz = __float2half_rn(v.z - __half2float(hz));
    __half lw = __float2half_rn(v.w - __half2float(hw));
    __half2* row = (__half2*)(g_Xcat + (size_t)i * KTOT);
    __half2 h0 = __halves2half2(hx, hy), h1 = __halves2half2(hz, hw);
    __half2 l0 = __halves2half2(lx, ly), l1 = __halves2half2(lz, lw);
    row[t * 2] = h0;       row[t * 2 + 1] = h1;
    row[128 + t * 2] = h0; row[128 + t * 2 + 1] = h1;
    row[256 + t * 2] = l0; row[256 + t * 2 + 1] = l1;
}

// ---------------- init: 0.5|c|^2, Bcat1, counters, dtype detect ----------------
__global__ void __launch_bounds__(256) init_kernel(const float* __restrict__ cents,
                                                   const void* __restrict__ prev) {
    int k = blockIdx.x, tid = threadIdx.x;
    float c = cents[k * D_DIM + tid];
    __half ch = __float2half_rn(c);
    __half cl = __float2half_rn(c - __half2float(ch));
    g_Bcat1[k * KTOT + tid] = ch;
    g_Bcat1[k * KTOT + 256 + tid] = cl;
    g_Bcat1[k * KTOT + 512 + tid] = ch;
    float s = c * c;
    #pragma unroll
    for (int off = 16; off > 0; off >>= 1) s += __shfl_down_sync(0xffffffffu, s, off);
    __shared__ float ws[8];
    if ((tid & 31) == 0) ws[tid >> 5] = s;
    __syncthreads();
    if (tid == 0) {
        float tot = 0.0f;
        #pragma unroll
        for (int j = 0; j < 8; j++) tot += ws[j];
        g_cch1[k] = 0.5f * tot;
        g_cnti[k] = 0;
    }
    if (k == 0 && tid == 0) {
        g_match = 1;
        const int* p32 = (const int*)prev;
        int is64 = 1;
        for (int j = 0; j < 64; j++)
            if (p32[2 * j + 1] != 0) { is64 = 0; break; }
        g_prev64 = is64;
    }
}

// ---------------- counting sort + gather mean ----------------
__global__ void __launch_bounds__(256) count_kernel(const void* __restrict__ prev) {
    __shared__ int cnt[K_C];
    int tid = threadIdx.x;
    for (int k = tid; k < K_C; k += 256) cnt[k] = 0;
    __syncthreads();
    int base = blockIdx.x * 1024;
    #pragma unroll
    for (int j = 0; j < 4; j++) {
        int i = base + j * 256 + tid;
        if (i < N_PTS) atomicAdd(&cnt[get_prev(prev, i)], 1);
    }
    __syncthreads();
    for (int k = tid; k < K_C; k += 256)
        if (cnt[k]) atomicAdd(&g_cnti[k], cnt[k]);
}

__global__ void __launch_bounds__(512) prefix_kernel() {
    __shared__ int s[K_C];
    int tid = threadIdx.x;
    int own = g_cnti[tid];
    s[tid] = own;
    __syncthreads();
    #pragma unroll
    for (int off = 1; off < K_C; off <<= 1) {
        int t = (tid >= off) ? s[tid - off] : 0;
        __syncthreads();
        s[tid] += t;
        __syncthreads();
    }
    g_start[tid] = s[tid] - own;
    g_cursor[tid] = s[tid] - own;
}

__global__ void __launch_bounds__(256) scatteridx_kernel(const void* __restrict__ prev) {
    int i = blockIdx.x * 256 + threadIdx.x;
    if (i >= N_PTS) return;
    int a = get_prev(prev, i);
    g_idx[atomicAdd(&g_cursor[a], 1)] = i;
}

__global__ void __launch_bounds__(256) sum_kernel(const float* __restrict__ x) {
    int k = blockIdx.x, tid = threadIdx.x;
    int c = g_cnti[k], s0 = g_start[k];
    __shared__ int sj[256];
    float acc = 0.0f;
    for (int b = 0; b < c; b += 256) {
        int m = min(256, c - b);
        __syncthreads();
        if (tid < m) sj[tid] = g_idx[s0 + b + tid];
        __syncthreads();
        for (int j = 0; j < m; j++)
            acc += x[(size_t)sj[j] * D_DIM + tid];
    }
    g_sums[k * D_DIM + tid] = acc;
}

// ---------------- finalize: EMA + Bcat2 + 0.5|c|^2 + outputs ----------------
__global__ void __launch_bounds__(256) finalize_kernel(const float* __restrict__ cents,
                                                       float* __restrict__ out) {
    int k = blockIdx.x, tid = threadIdx.x;
    int match = g_match;
    float c0 = cents[k * D_DIM + tid];
    float up;
    if (match) up = 0.01f * c0 + 0.99f * (g_sums[k * D_DIM + tid] / (float)g_cnti[k]);
    else       up = c0;
    out[N_PTS + 1 + k * D_DIM + tid] = up;
    __half ch = __float2half_rn(up);
    __half cl = __float2half_rn(up - __half2float(ch));
    g_Bcat2[k * KTOT + tid] = ch;
    g_Bcat2[k * KTOT + 256 + tid] = cl;
    g_Bcat2[k * KTOT + 512 + tid] = ch;
    float s = up * up;
    #pragma unroll
    for (int off = 16; off > 0; off >>= 1) s += __shfl_down_sync(0xffffffffu, s, off);
    __shared__ float ws[8];
    if ((tid & 31) == 0) ws[tid >> 5] = s;
    __syncthreads();
    if (tid == 0) {
        float tot = 0.0f;
        #pragma unroll
        for (int j = 0; j < 8; j++) tot += ws[j];
        g_cch2[k] = 0.5f * tot;
    }
    if (k == 0 && tid == 0) out[N_PTS] = match ? 1.0f : 0.0f;
}

// ---------------- mma.sync fp16 argmin pass ----------------
// CTA: 64 points x 512 centroids, K=768, chunks of 64, double-buffered cp.async.
template <int PASS>
__global__ void __launch_bounds__(256) mma_pass_kernel(const void* __restrict__ prev,
                                                       float* __restrict__ out) {
    extern __shared__ __align__(16) char smem[];
    const __half* Bc = (PASS == 2) ? g_Bcat2 : g_Bcat1;
    const float* cch = (PASS == 2) ? g_cch2 : g_cch1;

    uint32_t sb = smem_u32(smem);
    int tid = threadIdx.x;
    int lane = tid & 31, wid = tid >> 5;
    int wm = wid >> 2, wn = wid & 3;
    int i0 = blockIdx.x * MT;

    for (int k = tid; k < K_C; k += 256)
        *(float*)(smem + SCCH + k * 4) = cch[k];

    // ldmatrix base addresses per k-step (A: row lane&15, col-half lane>>4)
    uint32_t addrA[4], addrB[4];
    {
        uint32_t rA = (uint32_t)(wm * 32 + (lane & 15));
        uint32_t rB = (uint32_t)(wn * 128 + (lane & 15));
        uint32_t cA = (uint32_t)((lane >> 4) * 16);
        #pragma unroll
        for (int ks = 0; ks < 4; ks++) {
            addrA[ks] = sb + SA + sw128(rA * 128 + cA + ks * 32);
            addrB[ks] = sb + SB + sw128(rB * 128 + cA + ks * 32);
        }
    }

    float acc[128];
    #pragma unroll
    for (int e = 0; e < 128; e++) acc[e] = 0.0f;

    // ---- tile loader ----
    auto load_chunk = [&](int stage, int ch) {
        int kc0 = ch * KC;
        #pragma unroll
        for (int r2 = 0; r2 < 2; r2++) {
            int op = tid + r2 * 256;
            int row = op >> 3, g = op & 7;
            const __half* src = g_Xcat + (size_t)(i0 + row) * KTOT + kc0 + g * 8;
            cpasync16(sb + SA + stage * 8192 + sw128((uint32_t)(row * 128 + g * 16)), src);
        }
        #pragma unroll
        for (int j = 0; j < 16; j++) {
            int op = tid + j * 256;
            int row = op >> 3, g = op & 7;
            const __half* src = Bc + (size_t)row * KTOT + kc0 + g * 8;
            cpasync16(sb + SB + stage * 65536 + sw128((uint32_t)(row * 128 + g * 16)), src);
        }
    };

    load_chunk(0, 0);
    asm volatile("cp.async.commit_group;");

    #pragma unroll 1
    for (int ch = 0; ch < NCH; ch++) {
        if (ch + 1 < NCH) load_chunk((ch + 1) & 1, ch + 1);
        asm volatile("cp.async.commit_group;");
        asm volatile("cp.async.wait_group 1;");
        __syncthreads();

        uint32_t sOA = (ch & 1) * 8192, sOB = (ch & 1) * 65536;
        #pragma unroll
        for (int ks = 0; ks < 4; ks++) {
            uint32_t a[8];
            ldsm_x4(a, addrA[ks] + sOA);
            ldsm_x4(a + 4, addrA[ks] + sOA + 2048);
            #pragma unroll
            for (int nfp = 0; nfp < 8; nfp++) {
                uint32_t b[4];
                ldsm_x4(b, addrB[ks] + sOB + nfp * 2048);
                mma16816(&acc[(2 * nfp) * 4], a, b[0], b[2]);
                mma16816(&acc[(2 * nfp + 1) * 4], a, b[1], b[3]);
                mma16816(&acc[(16 + 2 * nfp) * 4], a + 4, b[0], b[2]);
                mma16816(&acc[(16 + 2 * nfp + 1) * 4], a + 4, b[1], b[3]);
            }
        }
        __syncthreads();
    }

    // ---- epilogue: argmax of (dot - 0.5|c|^2) over 512 cols ----
    const float* cchs = (const float*)(smem + SCCH);
    float* redv = (float*)(smem + SRV);
    int*   redi = (int*)(smem + SRI);
    float* redp = (float*)(smem + SRP);
    int g = lane >> 2, q = lane & 3;

    #pragma unroll
    for (int mf = 0; mf < 2; mf++) {
        #pragma unroll
        for (int rp = 0; rp < 2; rp++) {
            int rloc = wm * 32 + mf * 16 + rp * 8 + g;
            int gi = i0 + rloc;
            int pv = -1;
            if (PASS == 1 && gi < N_PTS) pv = get_prev(prev, gi);
            float bv = -3e38f; int bi = 0; float mp = -3e38f;
            #pragma unroll
            for (int nf = 0; nf < 16; nf++) {
                #pragma unroll
                for (int e = 0; e < 2; e++) {
                    float v = acc[((mf * 16 + nf) * 4) + rp * 2 + e];
                    int n = wn * 128 + nf * 8 + q * 2 + e;
                    float m = v - cchs[n];
                    if (m > bv || (m == bv && n < bi)) { bv = m; bi = n; }
                    if (PASS == 1 && n == pv) mp = m;
                }
            }
            #pragma unroll
            for (int off = 1; off <= 2; off <<= 1) {
                float ov = __shfl_xor_sync(0xffffffffu, bv, off);
                int   oi = __shfl_xor_sync(0xffffffffu, bi, off);
                float om = __shfl_xor_sync(0xffffffffu, mp, off);
                if (ov > bv || (ov == bv && oi < bi)) { bv = ov; bi = oi; }
                if (om > mp) mp = om;
            }
            if (q == 0) {
                redv[rloc * 4 + wn] = bv;
                redi[rloc * 4 + wn] = bi;
                redp[rloc * 4 + wn] = mp;
            }
        }
    }
    __syncthreads();

    if (tid < MT) {
        int gi = i0 + tid;
        float bv = -3e38f; int bi = 0; float mp = -3e38f;
        #pragma unroll
        for (int w = 0; w < 4; w++) {
            float ov = redv[tid * 4 + w];
            int   oi = redi[tid * 4 + w];
            if (ov > bv || (ov == bv && oi < bi)) { bv = ov; bi = oi; }
            float om = redp[tid * 4 + w];
            if (om > mp) mp = om;
        }
        if (gi < N_PTS) {
            if (PASS == 1) {
                g_assign1[gi] = bi;
                if (mp < bv - EPS_M) g_match = 0;
            } else {
                out[gi] = (float)(g_match ? bi : g_assign1[gi]);
            }
        }
    }
}

// ---------------- launch ----------------
extern "C" void kernel_launch(void* const* d_in, const int* in_sizes, int n_in,
                              void* d_out, int out_size) {
    const float* x     = (const float*)d_in[0];
    const float* cents = (const float*)d_in[1];
    const void*  prev  = d_in[2];
    float* out = (float*)d_out;

    cudaFuncSetAttribute(mma_pass_kernel<1>,
                         cudaFuncAttributeMaxDynamicSharedMemorySize, SM_TOT);
    cudaFuncSetAttribute(mma_pass_kernel<2>,
                         cudaFuncAttributeMaxDynamicSharedMemorySize, SM_TOT);

    init_kernel<<<K_C, 256>>>(cents, prev);
    xcat_kernel<<<(N_PAD * 64) / 256, 256>>>(x);
    count_kernel<<<(N_PTS + 1023) / 1024, 256>>>(prev);
    prefix_kernel<<<1, 512>>>();
    scatteridx_kernel<<<(N_PTS + 255) / 256, 256>>>(prev);
    sum_kernel<<<K_C, 256>>>(x);
    mma_pass_kernel<1><<<N_PAD / MT, 256, SM_TOT>>>(prev, out);
    finalize_kernel<<<K_C, 256>>>(cents, out);
    mma_pass_kernel<2><<<N_PAD / MT, 256, SM_TOT>>>(prev, out);
}

// round 4
// speedup vs baseline: 1.8878x; 1.0245x over previous
#include <cuda_runtime.h>
#include <cuda_fp16.h>
#include <cstdint>

#define N_PTS  100000
#define N_PAD  100096          // 782 * 128
#define K_C    512
#define D_DIM  256
#define KC     64
#define NCH    12
#define MT     128
#define EPS_M  0.02f

// ---------------- device scratch ----------------
__device__ __half g_Xs[(size_t)N_PAD * 512];      // [xh(256) | xl(256)]
__device__ __half g_Bs1[K_C * 512];               // [ch(256) | cl(256)] original
__device__ __half g_Bs2[K_C * 512];               // updated
__device__ float  g_sums[K_C * D_DIM];
__device__ int    g_cnti[K_C];
__device__ int    g_start[K_C];
__device__ int    g_cursor[K_C];
__device__ int    g_idx[N_PTS];
__device__ float  g_cch1[K_C];
__device__ float  g_cch2[K_C];
__device__ int    g_assign1[N_PTS];
__device__ int    g_match;
__device__ int    g_prev64;

// ---------------- helpers ----------------
__device__ __forceinline__ int get_prev(const void* prev, int i) {
    if (g_prev64) return (int)((const long long*)prev)[i];
    return ((const int*)prev)[i];
}
__device__ __forceinline__ uint32_t smem_u32(const void* p) {
    uint32_t a;
    asm("{ .reg .u64 t; cvta.to.shared.u64 t, %1; cvt.u32.u64 %0, t; }" : "=r"(a) : "l"(p));
    return a;
}
__device__ __forceinline__ uint32_t sw128(uint32_t o) { return o ^ ((o >> 3) & 0x70u); }
__device__ __forceinline__ void cpasync16(uint32_t s, const void* g) {
    asm volatile("cp.async.cg.shared.global [%0], [%1], 16;" :: "r"(s), "l"(g));
}
__device__ __forceinline__ void ldsm_x4(uint32_t* r, uint32_t addr) {
    asm volatile("ldmatrix.sync.aligned.m8n8.x4.shared.b16 {%0,%1,%2,%3}, [%4];"
                 : "=r"(r[0]), "=r"(r[1]), "=r"(r[2]), "=r"(r[3]) : "r"(addr));
}
__device__ __forceinline__ void mma16816(float* c, const uint32_t* a, uint32_t b0, uint32_t b1) {
    asm volatile("mma.sync.aligned.m16n8k16.row.col.f32.f16.f16.f32 "
                 "{%0,%1,%2,%3}, {%4,%5,%6,%7}, {%8,%9}, {%0,%1,%2,%3};"
                 : "+f"(c[0]), "+f"(c[1]), "+f"(c[2]), "+f"(c[3])
                 : "r"(a[0]), "r"(a[1]), "r"(a[2]), "r"(a[3]), "r"(b0), "r"(b1));
}

// ---------------- SMEM layout: 3-stage pipeline ----------------
#define SA     0               // 3 x 16384 (A: 128 rows x 128B)
#define SB     49152           // 3 x 32768 (B: 256 rows x 128B)
#define SCCH   147456          // 512 floats
#define SRV    149504          // float[128*2]
#define SRI    150528
#define SRP    151552
#define SM_TOT 152576

// ---------------- xcat: split x into fp16 [xh|xl] ----------------
__global__ void __launch_bounds__(256) xcat_kernel(const float* __restrict__ x) {
    int idx = blockIdx.x * 256 + threadIdx.x;
    int i = idx >> 6, t = idx & 63;
    if (i >= N_PAD) return;
    float4 v = make_float4(0.f, 0.f, 0.f, 0.f);
    if (i < N_PTS) v = *(const float4*)(x + (size_t)i * D_DIM + t * 4);
    __half hx = __float2half_rn(v.x), hy = __float2half_rn(v.y);
    __half hz = __float2half_rn(v.z), hw = __float2half_rn(v.w);
    __half lx = __float2half_rn(v.x - __half2float(hx));
    __half ly = __float2half_rn(v.y - __half2float(hy));
    __half lz = __float2half_rn(v.z - __half2float(hz));
    __half lw = __float2half_rn(v.w - __half2float(hw));
    __half2* row = (__half2*)(g_Xs + (size_t)i * 512);
    row[t * 2]       = __halves2half2(hx, hy);
    row[t * 2 + 1]   = __halves2half2(hz, hw);
    row[128 + t * 2]     = __halves2half2(lx, ly);
    row[128 + t * 2 + 1] = __halves2half2(lz, lw);
}

// ---------------- init: 0.5|c|^2, Bs1, counters, dtype detect ----------------
__global__ void __launch_bounds__(256) init_kernel(const float* __restrict__ cents,
                                                   const void* __restrict__ prev) {
    int k = blockIdx.x, tid = threadIdx.x;
    float c = cents[k * D_DIM + tid];
    __half ch = __float2half_rn(c);
    __half cl = __float2half_rn(c - __half2float(ch));
    g_Bs1[k * 512 + tid] = ch;
    g_Bs1[k * 512 + 256 + tid] = cl;
    float s = c * c;
    #pragma unroll
    for (int off = 16; off > 0; off >>= 1) s += __shfl_down_sync(0xffffffffu, s, off);
    __shared__ float ws[8];
    if ((tid & 31) == 0) ws[tid >> 5] = s;
    __syncthreads();
    if (tid == 0) {
        float tot = 0.0f;
        #pragma unroll
        for (int j = 0; j < 8; j++) tot += ws[j];
        g_cch1[k] = 0.5f * tot;
        g_cnti[k] = 0;
    }
    if (k == 0 && tid == 0) {
        g_match = 1;
        const int* p32 = (const int*)prev;
        int is64 = 1;
        for (int j = 0; j < 64; j++)
            if (p32[2 * j + 1] != 0) { is64 = 0; break; }
        g_prev64 = is64;
    }
}

// ---------------- counting sort + gather mean ----------------
__global__ void __launch_bounds__(256) count_kernel(const void* __restrict__ prev) {
    __shared__ int cnt[K_C];
    int tid = threadIdx.x;
    for (int k = tid; k < K_C; k += 256) cnt[k] = 0;
    __syncthreads();
    int base = blockIdx.x * 1024;
    #pragma unroll
    for (int j = 0; j < 4; j++) {
        int i = base + j * 256 + tid;
        if (i < N_PTS) atomicAdd(&cnt[get_prev(prev, i)], 1);
    }
    __syncthreads();
    for (int k = tid; k < K_C; k += 256)
        if (cnt[k]) atomicAdd(&g_cnti[k], cnt[k]);
}

__global__ void __launch_bounds__(512) prefix_kernel() {
    __shared__ int s[K_C];
    int tid = threadIdx.x;
    int own = g_cnti[tid];
    s[tid] = own;
    __syncthreads();
    #pragma unroll
    for (int off = 1; off < K_C; off <<= 1) {
        int t = (tid >= off) ? s[tid - off] : 0;
        __syncthreads();
        s[tid] += t;
        __syncthreads();
    }
    g_start[tid] = s[tid] - own;
    g_cursor[tid] = s[tid] - own;
}

__global__ void __launch_bounds__(256) scatteridx_kernel(const void* __restrict__ prev) {
    int i = blockIdx.x * 256 + threadIdx.x;
    if (i >= N_PTS) return;
    int a = get_prev(prev, i);
    g_idx[atomicAdd(&g_cursor[a], 1)] = i;
}

__global__ void __launch_bounds__(256) sum_kernel(const float* __restrict__ x) {
    int k = blockIdx.x, tid = threadIdx.x;
    int c = g_cnti[k], s0 = g_start[k];
    __shared__ int sj[256];
    float acc = 0.0f;
    for (int b = 0; b < c; b += 256) {
        int m = min(256, c - b);
        __syncthreads();
        if (tid < m) sj[tid] = g_idx[s0 + b + tid];
        __syncthreads();
        for (int j = 0; j < m; j++)
            acc += x[(size_t)sj[j] * D_DIM + tid];
    }
    g_sums[k * D_DIM + tid] = acc;
}

// ---------------- finalize: EMA + Bs2 + 0.5|c|^2 + outputs ----------------
__global__ void __launch_bounds__(256) finalize_kernel(const float* __restrict__ cents,
                                                       float* __restrict__ out) {
    int k = blockIdx.x, tid = threadIdx.x;
    int match = g_match;
    float c0 = cents[k * D_DIM + tid];
    float up;
    if (match) up = 0.01f * c0 + 0.99f * (g_sums[k * D_DIM + tid] / (float)g_cnti[k]);
    else       up = c0;
    out[N_PTS + 1 + k * D_DIM + tid] = up;
    __half ch = __float2half_rn(up);
    __half cl = __float2half_rn(up - __half2float(ch));
    g_Bs2[k * 512 + tid] = ch;
    g_Bs2[k * 512 + 256 + tid] = cl;
    float s = up * up;
    #pragma unroll
    for (int off = 16; off > 0; off >>= 1) s += __shfl_down_sync(0xffffffffu, s, off);
    __shared__ float ws[8];
    if ((tid & 31) == 0) ws[tid >> 5] = s;
    __syncthreads();
    if (tid == 0) {
        float tot = 0.0f;
        #pragma unroll
        for (int j = 0; j < 8; j++) tot += ws[j];
        g_cch2[k] = 0.5f * tot;
    }
    if (k == 0 && tid == 0) out[N_PTS] = match ? 1.0f : 0.0f;
}

// ---------------- mma.sync fp16 argmin pass ----------------
// CTA: 128 points x 512 cents (two 256-col halves), K=768 via chunk remap,
// 3-stage cp.async pipeline with one barrier per chunk.
template <int PASS>
__global__ void __launch_bounds__(256) mma_pass_kernel(const void* __restrict__ prev,
                                                       float* __restrict__ out) {
    extern __shared__ __align__(16) char smem[];
    const __half* Bs = (PASS == 2) ? g_Bs2 : g_Bs1;
    const float* cch = (PASS == 2) ? g_cch2 : g_cch1;

    uint32_t sb = smem_u32(smem);
    int tid = threadIdx.x;
    int lane = tid & 31, wid = tid >> 5;
    int wm = wid >> 1, wn = wid & 1;      // 4 M-warps x 2 N-warps
    int i0 = blockIdx.x * MT;
    int g = lane >> 2, q = lane & 3;

    for (int k = tid; k < K_C; k += 256)
        *(float*)(smem + SCCH + k * 4) = cch[k];

    uint32_t addrA[4], addrB[4];
    {
        uint32_t rA = (uint32_t)(wm * 32 + (lane & 15));
        uint32_t rB = (uint32_t)(wn * 128 + (lane & 15));
        uint32_t cA = (uint32_t)((lane >> 4) * 16);
        #pragma unroll
        for (int ks = 0; ks < 4; ks++) {
            addrA[ks] = sb + SA + sw128(rA * 128 + cA + ks * 32);
            addrB[ks] = sb + SB + sw128(rB * 128 + cA + ks * 32);
        }
    }

    float bv[2][2]; int bi[2][2]; float mp[2][2]; int pv[2][2];
    #pragma unroll
    for (int mf = 0; mf < 2; mf++)
        #pragma unroll
        for (int rp = 0; rp < 2; rp++) {
            bv[mf][rp] = -3e38f; bi[mf][rp] = 0; mp[mf][rp] = -3e38f; pv[mf][rp] = -1;
            if (PASS == 1) {
                int gi = i0 + wm * 32 + mf * 16 + rp * 8 + g;
                if (gi < N_PTS) pv[mf][rp] = get_prev(prev, gi);
            }
        }

    #pragma unroll
    for (int h = 0; h < 2; h++) {
        int hbase = h * 256;
        float acc[128];
        #pragma unroll
        for (int e = 0; e < 128; e++) acc[e] = 0.0f;

        auto load_chunk = [&](int ch, int stage) {
            int aoff = ((ch & 3) << 6) + (ch >= 8 ? 256 : 0);
            int boff = (ch < 4) ? (ch << 6)
                                : (ch < 8 ? ((ch - 4) << 6) + 256 : ((ch - 8) << 6));
            #pragma unroll
            for (int r = 0; r < 4; r++) {
                int op = tid + r * 256;
                int row = op >> 3, gg = op & 7;
                const __half* src = g_Xs + (size_t)(i0 + row) * 512 + aoff + gg * 8;
                cpasync16(sb + SA + stage * 16384 + sw128((uint32_t)(row * 128 + gg * 16)), src);
            }
            #pragma unroll
            for (int r = 0; r < 8; r++) {
                int op = tid + r * 256;
                int row = op >> 3, gg = op & 7;
                const __half* src = Bs + (size_t)(hbase + row) * 512 + boff + gg * 8;
                cpasync16(sb + SB + stage * 32768 + sw128((uint32_t)(row * 128 + gg * 16)), src);
            }
        };

        load_chunk(0, 0);
        asm volatile("cp.async.commit_group;");
        load_chunk(1, 1);
        asm volatile("cp.async.commit_group;");

        #pragma unroll 1
        for (int ch = 0; ch < NCH; ch++) {
            if (ch == NCH - 1) asm volatile("cp.async.wait_group 0;");
            else               asm volatile("cp.async.wait_group 1;");
            __syncthreads();

            int stage = ch % 3;
            uint32_t sOA = stage * 16384, sOB = stage * 32768;
            #pragma unroll
            for (int ks = 0; ks < 4; ks++) {
                uint32_t a[8];
                ldsm_x4(a, addrA[ks] + sOA);
                ldsm_x4(a + 4, addrA[ks] + sOA + 2048);
                #pragma unroll
                for (int nfp = 0; nfp < 8; nfp++) {
                    uint32_t b[4];
                    ldsm_x4(b, addrB[ks] + sOB + nfp * 2048);
                    mma16816(&acc[(2 * nfp) * 4], a, b[0], b[2]);
                    mma16816(&acc[(2 * nfp + 1) * 4], a, b[1], b[3]);
                    mma16816(&acc[(16 + 2 * nfp) * 4], a + 4, b[0], b[2]);
                    mma16816(&acc[(16 + 2 * nfp + 1) * 4], a + 4, b[1], b[3]);
                }
            }
            if (ch < NCH - 2) {
                load_chunk(ch + 2, (ch + 2) % 3);
                asm volatile("cp.async.commit_group;");
            }
        }

        // per-half epilogue: fold acc into running per-row best
        const float* cchs = (const float*)(smem + SCCH);
        #pragma unroll
        for (int mf = 0; mf < 2; mf++) {
            #pragma unroll
            for (int rp = 0; rp < 2; rp++) {
                #pragma unroll
                for (int nf = 0; nf < 16; nf++) {
                    #pragma unroll
                    for (int e = 0; e < 2; e++) {
                        float v = acc[(mf * 16 + nf) * 4 + rp * 2 + e];
                        int n = hbase + wn * 128 + nf * 8 + q * 2 + e;
                        float m = v - cchs[n];
                        if (m > bv[mf][rp] || (m == bv[mf][rp] && n < bi[mf][rp])) {
                            bv[mf][rp] = m; bi[mf][rp] = n;
                        }
                        if (PASS == 1 && n == pv[mf][rp]) mp[mf][rp] = m;
                    }
                }
            }
        }
        __syncthreads();   // all warps done reading stages before next half reloads
    }

    // ---- cross-lane + cross-warp reduce ----
    float* redv = (float*)(smem + SRV);
    int*   redi = (int*)(smem + SRI);
    float* redp = (float*)(smem + SRP);

    #pragma unroll
    for (int mf = 0; mf < 2; mf++) {
        #pragma unroll
        for (int rp = 0; rp < 2; rp++) {
            float v = bv[mf][rp]; int ix = bi[mf][rp]; float m = mp[mf][rp];
            #pragma unroll
            for (int off = 1; off <= 2; off <<= 1) {
                float ov = __shfl_xor_sync(0xffffffffu, v, off);
                int   oi = __shfl_xor_sync(0xffffffffu, ix, off);
                float om = __shfl_xor_sync(0xffffffffu, m, off);
                if (ov > v || (ov == v && oi < ix)) { v = ov; ix = oi; }
                if (om > m) m = om;
            }
            if (q == 0) {
                int rloc = wm * 32 + mf * 16 + rp * 8 + g;
                redv[rloc * 2 + wn] = v;
                redi[rloc * 2 + wn] = ix;
                redp[rloc * 2 + wn] = m;
            }
        }
    }
    __syncthreads();

    if (tid < MT) {
        int gi = i0 + tid;
        float v = redv[tid * 2]; int ix = redi[tid * 2]; float m = redp[tid * 2];
        float ov = redv[tid * 2 + 1]; int oi = redi[tid * 2 + 1];
        if (ov > v || (ov == v && oi < ix)) { v = ov; ix = oi; }
        float om = redp[tid * 2 + 1];
        if (om > m) m = om;
        if (gi < N_PTS) {
            if (PASS == 1) {
                g_assign1[gi] = ix;
                if (m < v - EPS_M) g_match = 0;
            } else {
                out[gi] = (float)(g_match ? ix : g_assign1[gi]);
            }
        }
    }
}

// ---------------- launch ----------------
extern "C" void kernel_launch(void* const* d_in, const int* in_sizes, int n_in,
                              void* d_out, int out_size) {
    const float* x     = (const float*)d_in[0];
    const float* cents = (const float*)d_in[1];
    const void*  prev  = d_in[2];
    float* out = (float*)d_out;

    cudaFuncSetAttribute(mma_pass_kernel<1>,
                         cudaFuncAttributeMaxDynamicSharedMemorySize, SM_TOT);
    cudaFuncSetAttribute(mma_pass_kernel<2>,
                         cudaFuncAttributeMaxDynamicSharedMemorySize, SM_TOT);

    init_kernel<<<K_C, 256>>>(cents, prev);
    xcat_kernel<<<(N_PAD * 64) / 256, 256>>>(x);
    count_kernel<<<(N_PTS + 1023) / 1024, 256>>>(prev);
    prefix_kernel<<<1, 512>>>();
    scatteridx_kernel<<<(N_PTS + 255) / 256, 256>>>(prev);
    sum_kernel<<<K_C, 256>>>(x);
    mma_pass_kernel<1><<<N_PAD / MT, 256, SM_TOT>>>(prev, out);
    finalize_kernel<<<K_C, 256>>>(cents, out);
    mma_pass_kernel<2><<<N_PAD / MT, 256, SM_TOT>>>(prev, out);
}

// round 5
// speedup vs baseline: 1.9886x; 1.0534x over previous
#include <cuda_runtime.h>
#include <cuda_fp16.h>
#include <cstdint>

#define N_PTS  100000
#define N_PAD  100096          // 782 * 128
#define K_C    512
#define D_DIM  256
#define NCH    4
#define MT     128
#define EPS_M  0.02f
#define BAND   0.5f
#define CAP    12

// ---------------- device scratch ----------------
__device__ __half g_Xh[(size_t)N_PAD * 256];      // fp16 hi of x
__device__ __half g_Bh1[K_C * 256];               // fp16 hi of centroids
__device__ __half g_Bh2[K_C * 256];               // fp16 hi of updated centroids
__device__ float  g_upd[K_C * D_DIM];             // updated centroids fp32
__device__ float  g_sums[K_C * D_DIM];
__device__ int    g_cnti[K_C];
__device__ int    g_start[K_C];
__device__ int    g_cursor[K_C];
__device__ int    g_idx[N_PTS];
__device__ float  g_cch1[K_C];
__device__ float  g_cch2[K_C];
__device__ int    g_assign1[N_PTS];
__device__ int    g_match;
__device__ int    g_prev64;

// ---------------- helpers ----------------
__device__ __forceinline__ int get_prev(const void* prev, int i) {
    if (g_prev64) return (int)((const long long*)prev)[i];
    return ((const int*)prev)[i];
}
__device__ __forceinline__ uint32_t smem_u32(const void* p) {
    uint32_t a;
    asm("{ .reg .u64 t; cvta.to.shared.u64 t, %1; cvt.u32.u64 %0, t; }" : "=r"(a) : "l"(p));
    return a;
}
__device__ __forceinline__ uint32_t sw128(uint32_t o) { return o ^ ((o >> 3) & 0x70u); }
__device__ __forceinline__ void cpasync16(uint32_t s, const void* g) {
    asm volatile("cp.async.cg.shared.global [%0], [%1], 16;" :: "r"(s), "l"(g));
}
__device__ __forceinline__ void ldsm_x4(uint32_t* r, uint32_t addr) {
    asm volatile("ldmatrix.sync.aligned.m8n8.x4.shared.b16 {%0,%1,%2,%3}, [%4];"
                 : "=r"(r[0]), "=r"(r[1]), "=r"(r[2]), "=r"(r[3]) : "r"(addr));
}
__device__ __forceinline__ void mma16816(float* c, const uint32_t* a, uint32_t b0, uint32_t b1) {
    asm volatile("mma.sync.aligned.m16n8k16.row.col.f32.f16.f16.f32 "
                 "{%0,%1,%2,%3}, {%4,%5,%6,%7}, {%8,%9}, {%0,%1,%2,%3};"
                 : "+f"(c[0]), "+f"(c[1]), "+f"(c[2]), "+f"(c[3])
                 : "r"(a[0]), "r"(a[1]), "r"(a[2]), "r"(a[3]), "r"(b0), "r"(b1));
}
// full-warp butterfly sum
__device__ __forceinline__ float warp_sum(float v) {
    #pragma unroll
    for (int off = 16; off > 0; off >>= 1) v += __shfl_xor_sync(0xffffffffu, v, off);
    return v;
}

// ---------------- SMEM layout ----------------
#define SA      0               // 3 x 16384
#define SB      49152           // 3 x 32768
#define SCCH    147456          // 512 floats
#define SRV     149504          // 128*2 floats
#define SRMAX   150528          // 2*128 floats
#define SCNT    151552          // 128 ints
#define SCANDK  152064          // 128*CAP ints
#define SCANDM  158208          // 128*CAP floats
#define SM_TOT  164352

// ---------------- xcat: x -> fp16 hi ----------------
__global__ void __launch_bounds__(256) xcat_kernel(const float* __restrict__ x) {
    int idx = blockIdx.x * 256 + threadIdx.x;
    int i = idx >> 6, t = idx & 63;
    if (i >= N_PAD) return;
    float4 v = make_float4(0.f, 0.f, 0.f, 0.f);
    if (i < N_PTS) v = *(const float4*)(x + (size_t)i * D_DIM + t * 4);
    __half2* row = (__half2*)(g_Xh + (size_t)i * 256);
    row[t * 2]     = __halves2half2(__float2half_rn(v.x), __float2half_rn(v.y));
    row[t * 2 + 1] = __halves2half2(__float2half_rn(v.z), __float2half_rn(v.w));
}

// ---------------- init ----------------
__global__ void __launch_bounds__(256) init_kernel(const float* __restrict__ cents,
                                                   const void* __restrict__ prev) {
    int k = blockIdx.x, tid = threadIdx.x;
    float c = cents[k * D_DIM + tid];
    g_Bh1[k * 256 + tid] = __float2half_rn(c);
    float s = c * c;
    #pragma unroll
    for (int off = 16; off > 0; off >>= 1) s += __shfl_down_sync(0xffffffffu, s, off);
    __shared__ float ws[8];
    if ((tid & 31) == 0) ws[tid >> 5] = s;
    __syncthreads();
    if (tid == 0) {
        float tot = 0.0f;
        #pragma unroll
        for (int j = 0; j < 8; j++) tot += ws[j];
        g_cch1[k] = 0.5f * tot;
        g_cnti[k] = 0;
    }
    if (k == 0 && tid == 0) {
        g_match = 1;
        const int* p32 = (const int*)prev;
        int is64 = 1;
        for (int j = 0; j < 64; j++)
            if (p32[2 * j + 1] != 0) { is64 = 0; break; }
        g_prev64 = is64;
    }
}

// ---------------- counting sort + gather mean ----------------
__global__ void __launch_bounds__(256) count_kernel(const void* __restrict__ prev) {
    __shared__ int cnt[K_C];
    int tid = threadIdx.x;
    for (int k = tid; k < K_C; k += 256) cnt[k] = 0;
    __syncthreads();
    int base = blockIdx.x * 1024;
    #pragma unroll
    for (int j = 0; j < 4; j++) {
        int i = base + j * 256 + tid;
        if (i < N_PTS) atomicAdd(&cnt[get_prev(prev, i)], 1);
    }
    __syncthreads();
    for (int k = tid; k < K_C; k += 256)
        if (cnt[k]) atomicAdd(&g_cnti[k], cnt[k]);
}

__global__ void __launch_bounds__(512) prefix_kernel() {
    __shared__ int s[K_C];
    int tid = threadIdx.x;
    int own = g_cnti[tid];
    s[tid] = own;
    __syncthreads();
    #pragma unroll
    for (int off = 1; off < K_C; off <<= 1) {
        int t = (tid >= off) ? s[tid - off] : 0;
        __syncthreads();
        s[tid] += t;
        __syncthreads();
    }
    g_start[tid] = s[tid] - own;
    g_cursor[tid] = s[tid] - own;
}

__global__ void __launch_bounds__(256) scatteridx_kernel(const void* __restrict__ prev) {
    int i = blockIdx.x * 256 + threadIdx.x;
    if (i >= N_PTS) return;
    g_idx[atomicAdd(&g_cursor[get_prev(prev, i)], 1)] = i;
}

__global__ void __launch_bounds__(256) sum_kernel(const float* __restrict__ x) {
    int k = blockIdx.x, tid = threadIdx.x;
    int c = g_cnti[k], s0 = g_start[k];
    __shared__ int sj[256];
    float acc = 0.0f;
    for (int b = 0; b < c; b += 256) {
        int m = min(256, c - b);
        __syncthreads();
        if (tid < m) sj[tid] = g_idx[s0 + b + tid];
        __syncthreads();
        for (int j = 0; j < m; j++)
            acc += x[(size_t)sj[j] * D_DIM + tid];
    }
    g_sums[k * D_DIM + tid] = acc;
}

// ---------------- finalize ----------------
__global__ void __launch_bounds__(256) finalize_kernel(const float* __restrict__ cents,
                                                       float* __restrict__ out) {
    int k = blockIdx.x, tid = threadIdx.x;
    int match = g_match;
    float c0 = cents[k * D_DIM + tid];
    float up;
    if (match) up = 0.01f * c0 + 0.99f * (g_sums[k * D_DIM + tid] / (float)g_cnti[k]);
    else       up = c0;
    g_upd[k * D_DIM + tid] = up;
    out[N_PTS + 1 + k * D_DIM + tid] = up;
    g_Bh2[k * 256 + tid] = __float2half_rn(up);
    float s = up * up;
    #pragma unroll
    for (int off = 16; off > 0; off >>= 1) s += __shfl_down_sync(0xffffffffu, s, off);
    __shared__ float ws[8];
    if ((tid & 31) == 0) ws[tid >> 5] = s;
    __syncthreads();
    if (tid == 0) {
        float tot = 0.0f;
        #pragma unroll
        for (int j = 0; j < 8; j++) tot += ws[j];
        g_cch2[k] = 0.5f * tot;
    }
    if (k == 0 && tid == 0) out[N_PTS] = match ? 1.0f : 0.0f;
}

// ---------------- screen (fp16 K=256) + exact rescore pass ----------------
template <int PASS>
__global__ void __launch_bounds__(256) mma_pass_kernel(const float* __restrict__ x,
                                                       const float* __restrict__ cents_in,
                                                       const void* __restrict__ prev,
                                                       float* __restrict__ out) {
    extern __shared__ __align__(16) char smem[];
    const __half* Bh  = (PASS == 2) ? g_Bh2 : g_Bh1;
    const float* cch  = (PASS == 2) ? g_cch2 : g_cch1;
    const float* cfp  = (PASS == 2) ? g_upd : cents_in;

    uint32_t sb = smem_u32(smem);
    int tid = threadIdx.x;
    int lane = tid & 31, wid = tid >> 5;
    int wm = wid >> 1, wn = wid & 1;
    int i0 = blockIdx.x * MT;
    int g = lane >> 2, q = lane & 3;

    float* cchs = (float*)(smem + SCCH);
    float* redv = (float*)(smem + SRV);
    float* srmax = (float*)(smem + SRMAX);
    int*   scnt = (int*)(smem + SCNT);
    int*   candk = (int*)(smem + SCANDK);
    float* candm = (float*)(smem + SCANDM);

    for (int k = tid; k < K_C; k += 256) cchs[k] = cch[k];
    if (tid < MT) scnt[tid] = 0;

    uint32_t addrA[4], addrB[4];
    {
        uint32_t rA = (uint32_t)(wm * 32 + (lane & 15));
        uint32_t rB = (uint32_t)(wn * 128 + (lane & 15));
        uint32_t cA = (uint32_t)((lane >> 4) * 16);
        #pragma unroll
        for (int ks = 0; ks < 4; ks++) {
            addrA[ks] = sb + SA + sw128(rA * 128 + cA + ks * 32);
            addrB[ks] = sb + SB + sw128(rB * 128 + cA + ks * 32);
        }
    }
    __syncthreads();

    #pragma unroll
    for (int h = 0; h < 2; h++) {
        int hbase = h * 256;
        float acc[128];
        #pragma unroll
        for (int e = 0; e < 128; e++) acc[e] = 0.0f;

        auto load_chunk = [&](int ch, int stage) {
            int koff = ch * 64;
            #pragma unroll
            for (int r = 0; r < 4; r++) {
                int op = tid + r * 256;
                int row = op >> 3, gg = op & 7;
                const __half* src = g_Xh + (size_t)(i0 + row) * 256 + koff + gg * 8;
                cpasync16(sb + SA + stage * 16384 + sw128((uint32_t)(row * 128 + gg * 16)), src);
            }
            #pragma unroll
            for (int r = 0; r < 8; r++) {
                int op = tid + r * 256;
                int row = op >> 3, gg = op & 7;
                const __half* src = Bh + (size_t)(hbase + row) * 256 + koff + gg * 8;
                cpasync16(sb + SB + stage * 32768 + sw128((uint32_t)(row * 128 + gg * 16)), src);
            }
        };

        load_chunk(0, 0);
        asm volatile("cp.async.commit_group;");
        load_chunk(1, 1);
        asm volatile("cp.async.commit_group;");

        #pragma unroll 1
        for (int ch = 0; ch < NCH; ch++) {
            if (ch == NCH - 1) asm volatile("cp.async.wait_group 0;");
            else               asm volatile("cp.async.wait_group 1;");
            __syncthreads();
            int stage = ch % 3;
            uint32_t sOA = stage * 16384, sOB = stage * 32768;
            #pragma unroll
            for (int ks = 0; ks < 4; ks++) {
                uint32_t a[8];
                ldsm_x4(a, addrA[ks] + sOA);
                ldsm_x4(a + 4, addrA[ks] + sOA + 2048);
                #pragma unroll
                for (int nfp = 0; nfp < 8; nfp++) {
                    uint32_t b[4];
                    ldsm_x4(b, addrB[ks] + sOB + nfp * 2048);
                    mma16816(&acc[(2 * nfp) * 4], a, b[0], b[2]);
                    mma16816(&acc[(2 * nfp + 1) * 4], a, b[1], b[3]);
                    mma16816(&acc[(16 + 2 * nfp) * 4], a + 4, b[0], b[2]);
                    mma16816(&acc[(16 + 2 * nfp + 1) * 4], a + 4, b[1], b[3]);
                }
            }
            if (ch < NCH - 2) {
                load_chunk(ch + 2, (ch + 2) % 3);
                asm volatile("cp.async.commit_group;");
            }
        }

        // ---- per-half approximate row max ----
        float tmax[2][2];
        #pragma unroll
        for (int mf = 0; mf < 2; mf++)
            #pragma unroll
            for (int rp = 0; rp < 2; rp++) {
                float bm = -3e38f;
                #pragma unroll
                for (int nf = 0; nf < 16; nf++)
                    #pragma unroll
                    for (int e = 0; e < 2; e++) {
                        int n = hbase + wn * 128 + nf * 8 + q * 2 + e;
                        float m = acc[(mf * 16 + nf) * 4 + rp * 2 + e] - cchs[n];
                        acc[(mf * 16 + nf) * 4 + rp * 2 + e] = m;   // keep m, not dot
                        if (m > bm) bm = m;
                    }
                tmax[mf][rp] = bm;
            }
        #pragma unroll
        for (int mf = 0; mf < 2; mf++)
            #pragma unroll
            for (int rp = 0; rp < 2; rp++) {
                float v = tmax[mf][rp];
                #pragma unroll
                for (int off = 1; off <= 2; off <<= 1)
                    v = fmaxf(v, __shfl_xor_sync(0xffffffffu, v, off));
                if (q == 0) {
                    int rloc = wm * 32 + mf * 16 + rp * 8 + g;
                    redv[rloc * 2 + wn] = v;
                }
            }
        __syncthreads();
        if (wn == 0 && q == 0) {
            #pragma unroll
            for (int mf = 0; mf < 2; mf++)
                #pragma unroll
                for (int rp = 0; rp < 2; rp++) {
                    int rloc = wm * 32 + mf * 16 + rp * 8 + g;
                    srmax[h * 128 + rloc] = fmaxf(redv[rloc * 2], redv[rloc * 2 + 1]);
                }
        }
        __syncthreads();

        // ---- candidate scan ----
        #pragma unroll
        for (int mf = 0; mf < 2; mf++)
            #pragma unroll
            for (int rp = 0; rp < 2; rp++) {
                int rloc = wm * 32 + mf * 16 + rp * 8 + g;
                float thr = srmax[h * 128 + rloc] - BAND;
                #pragma unroll
                for (int nf = 0; nf < 16; nf++)
                    #pragma unroll
                    for (int e = 0; e < 2; e++) {
                        float m = acc[(mf * 16 + nf) * 4 + rp * 2 + e];
                        if (m >= thr) {
                            int n = hbase + wn * 128 + nf * 8 + q * 2 + e;
                            int slot = atomicAdd(&scnt[rloc], 1);
                            if (slot < CAP) {
                                candk[rloc * CAP + slot] = n;
                                candm[rloc * CAP + slot] = m;
                            }
                        }
                    }
            }
        __syncthreads();
    }

    // ---- exact fp32 rescore: warp wid handles rows wid*16..wid*16+15 ----
    for (int rr = 0; rr < 16; rr++) {
        int rloc = wid * 16 + rr;
        int gi = i0 + rloc;
        if (gi >= N_PTS) continue;

        float xr[8];
        {
            const float4* xp = (const float4*)(x + (size_t)gi * D_DIM + lane * 8);
            float4 v0 = xp[0], v1 = xp[1];
            xr[0] = v0.x; xr[1] = v0.y; xr[2] = v0.z; xr[3] = v0.w;
            xr[4] = v1.x; xr[5] = v1.y; xr[6] = v1.z; xr[7] = v1.w;
        }
        float rmax = fmaxf(srmax[rloc], srmax[128 + rloc]);
        int cnt = scnt[rloc];
        float bv = -3e38f; int bi = 0;

        if (cnt > CAP) {
            for (int k = 0; k < K_C; k++) {
                const float4* cp = (const float4*)(cfp + (size_t)k * D_DIM + lane * 8);
                float4 c0 = cp[0], c1 = cp[1];
                float d = xr[0]*c0.x + xr[1]*c0.y + xr[2]*c0.z + xr[3]*c0.w
                        + xr[4]*c1.x + xr[5]*c1.y + xr[6]*c1.z + xr[7]*c1.w;
                float m = warp_sum(d) - cchs[k];
                if (m > bv || (m == bv && k < bi)) { bv = m; bi = k; }
            }
        } else {
            for (int j = 0; j < cnt; j++) {
                if (candm[rloc * CAP + j] < rmax - BAND) continue;
                int k = candk[rloc * CAP + j];
                const float4* cp = (const float4*)(cfp + (size_t)k * D_DIM + lane * 8);
                float4 c0 = cp[0], c1 = cp[1];
                float d = xr[0]*c0.x + xr[1]*c0.y + xr[2]*c0.z + xr[3]*c0.w
                        + xr[4]*c1.x + xr[5]*c1.y + xr[6]*c1.z + xr[7]*c1.w;
                float m = warp_sum(d) - cchs[k];
                if (m > bv || (m == bv && k < bi)) { bv = m; bi = k; }
            }
        }

        if (PASS == 1) {
            int pv = get_prev(prev, gi);
            const float4* cp = (const float4*)(cfp + (size_t)pv * D_DIM + lane * 8);
            float4 c0 = cp[0], c1 = cp[1];
            float d = xr[0]*c0.x + xr[1]*c0.y + xr[2]*c0.z + xr[3]*c0.w
                    + xr[4]*c1.x + xr[5]*c1.y + xr[6]*c1.z + xr[7]*c1.w;
            float mprev = warp_sum(d) - cchs[pv];
            if (lane == 0) {
                g_assign1[gi] = bi;
                if (mprev < bv - EPS_M) g_match = 0;
            }
        } else {
            if (lane == 0) out[gi] = (float)(g_match ? bi : g_assign1[gi]);
        }
    }
}

// ---------------- launch ----------------
extern "C" void kernel_launch(void* const* d_in, const int* in_sizes, int n_in,
                              void* d_out, int out_size) {
    const float* x     = (const float*)d_in[0];
    const float* cents = (const float*)d_in[1];
    const void*  prev  = d_in[2];
    float* out = (float*)d_out;

    cudaFuncSetAttribute(mma_pass_kernel<1>,
                         cudaFuncAttributeMaxDynamicSharedMemorySize, SM_TOT);
    cudaFuncSetAttribute(mma_pass_kernel<2>,
                         cudaFuncAttributeMaxDynamicSharedMemorySize, SM_TOT);

    init_kernel<<<K_C, 256>>>(cents, prev);
    xcat_kernel<<<(N_PAD * 64) / 256, 256>>>(x);
    count_kernel<<<(N_PTS + 1023) / 1024, 256>>>(prev);
    prefix_kernel<<<1, 512>>>();
    scatteridx_kernel<<<(N_PTS + 255) / 256, 256>>>(prev);
    sum_kernel<<<K_C, 256>>>(x);
    mma_pass_kernel<1><<<N_PAD / MT, 256, SM_TOT>>>(x, cents, prev, out);
    finalize_kernel<<<K_C, 256>>>(cents, out);
    mma_pass_kernel<2><<<N_PAD / MT, 256, SM_TOT>>>(x, cents, prev, out);
}

// round 7
// speedup vs baseline: 2.0038x; 1.0076x over previous
#include <cuda_runtime.h>
#include <cuda_fp16.h>
#include <cstdint>

#define N_PTS  100000
#define N_PAD  100096          // 782 * 128
#define K_C    512
#define D_DIM  256
#define NCH    4
#define MT     128
#define EPS_M  0.02f
#define BAND   0.5f
#define CAP    12

// ---------------- device scratch ----------------
__device__ __half g_Xh[(size_t)N_PAD * 256];      // fp16 hi of x
__device__ __half g_Bh1[K_C * 256];               // fp16 hi of centroids
__device__ __half g_Bh2[K_C * 256];               // fp16 hi of updated centroids
__device__ float  g_upd[K_C * D_DIM];             // updated centroids fp32
__device__ float  g_sums[K_C * D_DIM];
__device__ int    g_cnti[K_C];
__device__ int    g_start[K_C];
__device__ int    g_cursor[K_C];
__device__ int    g_idx[N_PTS];
__device__ float  g_cch1[K_C];
__device__ float  g_cch2[K_C];
__device__ int    g_assign1[N_PTS];
__device__ int    g_match;
__device__ int    g_prev64;

// ---------------- helpers ----------------
__device__ __forceinline__ int get_prev(const void* prev, int i) {
    if (g_prev64) return (int)((const long long*)prev)[i];
    return ((const int*)prev)[i];
}
__device__ __forceinline__ uint32_t smem_u32(const void* p) {
    uint32_t a;
    asm("{ .reg .u64 t; cvta.to.shared.u64 t, %1; cvt.u32.u64 %0, t; }" : "=r"(a) : "l"(p));
    return a;
}
__device__ __forceinline__ uint32_t sw128(uint32_t o) { return o ^ ((o >> 3) & 0x70u); }
__device__ __forceinline__ void cpasync16(uint32_t s, const void* g) {
    asm volatile("cp.async.cg.shared.global [%0], [%1], 16;" :: "r"(s), "l"(g));
}
__device__ __forceinline__ void ldsm_x4(uint32_t* r, uint32_t addr) {
    asm volatile("ldmatrix.sync.aligned.m8n8.x4.shared.b16 {%0,%1,%2,%3}, [%4];"
                 : "=r"(r[0]), "=r"(r[1]), "=r"(r[2]), "=r"(r[3]) : "r"(addr));
}
__device__ __forceinline__ void mma16816(float* c, const uint32_t* a, uint32_t b0, uint32_t b1) {
    asm volatile("mma.sync.aligned.m16n8k16.row.col.f32.f16.f16.f32 "
                 "{%0,%1,%2,%3}, {%4,%5,%6,%7}, {%8,%9}, {%0,%1,%2,%3};"
                 : "+f"(c[0]), "+f"(c[1]), "+f"(c[2]), "+f"(c[3])
                 : "r"(a[0]), "r"(a[1]), "r"(a[2]), "r"(a[3]), "r"(b0), "r"(b1));
}
// full-warp butterfly sum
__device__ __forceinline__ float warp_sum(float v) {
    #pragma unroll
    for (int off = 16; off > 0; off >>= 1) v += __shfl_xor_sync(0xffffffffu, v, off);
    return v;
}

// ---------------- SMEM layout ----------------
#define SA      0               // 3 x 16384
#define SB      49152           // 3 x 32768
#define SCCH    147456          // 512 floats
#define SRV     149504          // 128*2 floats
#define SRMAX   150528          // 2*128 floats
#define SCNT    151552          // 128 ints
#define SCANDK  152064          // 128*CAP ints
#define SCANDM  158208          // 128*CAP floats
#define SM_TOT  164352

// ---------------- xcat: x -> fp16 hi ----------------
__global__ void __launch_bounds__(256) xcat_kernel(const float* __restrict__ x) {
    int idx = blockIdx.x * 256 + threadIdx.x;
    int i = idx >> 6, t = idx & 63;
    if (i >= N_PAD) return;
    float4 v = make_float4(0.f, 0.f, 0.f, 0.f);
    if (i < N_PTS) v = *(const float4*)(x + (size_t)i * D_DIM + t * 4);
    __half2* row = (__half2*)(g_Xh + (size_t)i * 256);
    row[t * 2]     = __halves2half2(__float2half_rn(v.x), __float2half_rn(v.y));
    row[t * 2 + 1] = __halves2half2(__float2half_rn(v.z), __float2half_rn(v.w));
}

// ---------------- init ----------------
__global__ void __launch_bounds__(256) init_kernel(const float* __restrict__ cents,
                                                   const void* __restrict__ prev) {
    int k = blockIdx.x, tid = threadIdx.x;
    float c = cents[k * D_DIM + tid];
    g_Bh1[k * 256 + tid] = __float2half_rn(c);
    float s = c * c;
    #pragma unroll
    for (int off = 16; off > 0; off >>= 1) s += __shfl_down_sync(0xffffffffu, s, off);
    __shared__ float ws[8];
    if ((tid & 31) == 0) ws[tid >> 5] = s;
    __syncthreads();
    if (tid == 0) {
        float tot = 0.0f;
        #pragma unroll
        for (int j = 0; j < 8; j++) tot += ws[j];
        g_cch1[k] = 0.5f * tot;
        g_cnti[k] = 0;
    }
    if (k == 0 && tid == 0) {
        g_match = 1;
        const int* p32 = (const int*)prev;
        int is64 = 1;
        for (int j = 0; j < 64; j++)
            if (p32[2 * j + 1] != 0) { is64 = 0; break; }
        g_prev64 = is64;
    }
}

// ---------------- counting sort + gather mean ----------------
__global__ void __launch_bounds__(256) count_kernel(const void* __restrict__ prev) {
    __shared__ int cnt[K_C];
    int tid = threadIdx.x;
    for (int k = tid; k < K_C; k += 256) cnt[k] = 0;
    __syncthreads();
    int base = blockIdx.x * 1024;
    #pragma unroll
    for (int j = 0; j < 4; j++) {
        int i = base + j * 256 + tid;
        if (i < N_PTS) atomicAdd(&cnt[get_prev(prev, i)], 1);
    }
    __syncthreads();
    for (int k = tid; k < K_C; k += 256)
        if (cnt[k]) atomicAdd(&g_cnti[k], cnt[k]);
}

__global__ void __launch_bounds__(512) prefix_kernel() {
    __shared__ int s[K_C];
    int tid = threadIdx.x;
    int own = g_cnti[tid];
    s[tid] = own;
    __syncthreads();
    #pragma unroll
    for (int off = 1; off < K_C; off <<= 1) {
        int t = (tid >= off) ? s[tid - off] : 0;
        __syncthreads();
        s[tid] += t;
        __syncthreads();
    }
    g_start[tid] = s[tid] - own;
    g_cursor[tid] = s[tid] - own;
}

__global__ void __launch_bounds__(256) scatteridx_kernel(const void* __restrict__ prev) {
    int i = blockIdx.x * 256 + threadIdx.x;
    if (i >= N_PTS) return;
    g_idx[atomicAdd(&g_cursor[get_prev(prev, i)], 1)] = i;
}

__global__ void __launch_bounds__(256) sum_kernel(const float* __restrict__ x) {
    int k = blockIdx.x, tid = threadIdx.x;
    int c = g_cnti[k], s0 = g_start[k];
    __shared__ int sj[256];
    float acc = 0.0f;
    for (int b = 0; b < c; b += 256) {
        int m = min(256, c - b);
        __syncthreads();
        if (tid < m) sj[tid] = g_idx[s0 + b + tid];
        __syncthreads();
        for (int j = 0; j < m; j++)
            acc += x[(size_t)sj[j] * D_DIM + tid];
    }
    g_sums[k * D_DIM + tid] = acc;
}

// ---------------- finalize ----------------
__global__ void __launch_bounds__(256) finalize_kernel(const float* __restrict__ cents,
                                                       float* __restrict__ out) {
    int k = blockIdx.x, tid = threadIdx.x;
    int match = g_match;
    float c0 = cents[k * D_DIM + tid];
    float up;
    if (match) up = 0.01f * c0 + 0.99f * (g_sums[k * D_DIM + tid] / (float)g_cnti[k]);
    else       up = c0;
    g_upd[k * D_DIM + tid] = up;
    out[N_PTS + 1 + k * D_DIM + tid] = up;
    g_Bh2[k * 256 + tid] = __float2half_rn(up);
    float s = up * up;
    #pragma unroll
    for (int off = 16; off > 0; off >>= 1) s += __shfl_down_sync(0xffffffffu, s, off);
    __shared__ float ws[8];
    if ((tid & 31) == 0) ws[tid >> 5] = s;
    __syncthreads();
    if (tid == 0) {
        float tot = 0.0f;
        #pragma unroll
        for (int j = 0; j < 8; j++) tot += ws[j];
        g_cch2[k] = 0.5f * tot;
    }
    if (k == 0 && tid == 0) out[N_PTS] = match ? 1.0f : 0.0f;
}

// ---------------- screen (fp16 K=256) + exact rescore pass ----------------
// __launch_bounds__(256, 1): smem already forces 1 CTA/SM; without the
// explicit minBlocks, ptxas targets 2 CTAs/SM and spills ~90 regs.
template <int PASS>
__global__ void __launch_bounds__(256, 1) mma_pass_kernel(const float* __restrict__ x,
                                                          const float* __restrict__ cents_in,
                                                          const void* __restrict__ prev,
                                                          float* __restrict__ out) {
    extern __shared__ __align__(16) char smem[];
    const __half* Bh  = (PASS == 2) ? g_Bh2 : g_Bh1;
    const float* cch  = (PASS == 2) ? g_cch2 : g_cch1;
    const float* cfp  = (PASS == 2) ? g_upd : cents_in;

    uint32_t sb = smem_u32(smem);
    int tid = threadIdx.x;
    int lane = tid & 31, wid = tid >> 5;
    int wm = wid >> 1, wn = wid & 1;
    int i0 = blockIdx.x * MT;
    int g = lane >> 2, q = lane & 3;

    float* cchs = (float*)(smem + SCCH);
    float* redv = (float*)(smem + SRV);
    float* srmax = (float*)(smem + SRMAX);
    int*   scnt = (int*)(smem + SCNT);
    int*   candk = (int*)(smem + SCANDK);
    float* candm = (float*)(smem + SCANDM);

    for (int k = tid; k < K_C; k += 256) cchs[k] = cch[k];
    if (tid < MT) scnt[tid] = 0;

    uint32_t addrA[4], addrB[4];
    {
        uint32_t rA = (uint32_t)(wm * 32 + (lane & 15));
        uint32_t rB = (uint32_t)(wn * 128 + (lane & 15));
        uint32_t cA = (uint32_t)((lane >> 4) * 16);
        #pragma unroll
        for (int ks = 0; ks < 4; ks++) {
            addrA[ks] = sb + SA + sw128(rA * 128 + cA + ks * 32);
            addrB[ks] = sb + SB + sw128(rB * 128 + cA + ks * 32);
        }
    }
    __syncthreads();

    #pragma unroll
    for (int h = 0; h < 2; h++) {
        int hbase = h * 256;
        float acc[128];
        #pragma unroll
        for (int e = 0; e < 128; e++) acc[e] = 0.0f;

        auto load_chunk = [&](int ch, int stage) {
            int koff = ch * 64;
            #pragma unroll
            for (int r = 0; r < 4; r++) {
                int op = tid + r * 256;
                int row = op >> 3, gg = op & 7;
                const __half* src = g_Xh + (size_t)(i0 + row) * 256 + koff + gg * 8;
                cpasync16(sb + SA + stage * 16384 + sw128((uint32_t)(row * 128 + gg * 16)), src);
            }
            #pragma unroll
            for (int r = 0; r < 8; r++) {
                int op = tid + r * 256;
                int row = op >> 3, gg = op & 7;
                const __half* src = Bh + (size_t)(hbase + row) * 256 + koff + gg * 8;
                cpasync16(sb + SB + stage * 32768 + sw128((uint32_t)(row * 128 + gg * 16)), src);
            }
        };

        load_chunk(0, 0);
        asm volatile("cp.async.commit_group;");
        load_chunk(1, 1);
        asm volatile("cp.async.commit_group;");

        #pragma unroll 1
        for (int ch = 0; ch < NCH; ch++) {
            if (ch == NCH - 1) asm volatile("cp.async.wait_group 0;");
            else               asm volatile("cp.async.wait_group 1;");
            __syncthreads();
            int stage = ch % 3;
            uint32_t sOA = stage * 16384, sOB = stage * 32768;
            #pragma unroll
            for (int ks = 0; ks < 4; ks++) {
                uint32_t a[8];
                ldsm_x4(a, addrA[ks] + sOA);
                ldsm_x4(a + 4, addrA[ks] + sOA + 2048);
                #pragma unroll
                for (int nfp = 0; nfp < 8; nfp++) {
                    uint32_t b[4];
                    ldsm_x4(b, addrB[ks] + sOB + nfp * 2048);
                    mma16816(&acc[(2 * nfp) * 4], a, b[0], b[2]);
                    mma16816(&acc[(2 * nfp + 1) * 4], a, b[1], b[3]);
                    mma16816(&acc[(16 + 2 * nfp) * 4], a + 4, b[0], b[2]);
                    mma16816(&acc[(16 + 2 * nfp + 1) * 4], a + 4, b[1], b[3]);
                }
            }
            if (ch < NCH - 2) {
                load_chunk(ch + 2, (ch + 2) % 3);
                asm volatile("cp.async.commit_group;");
            }
        }

        // ---- per-half approximate row max ----
        float tmax[2][2];
        #pragma unroll
        for (int mf = 0; mf < 2; mf++)
            #pragma unroll
            for (int rp = 0; rp < 2; rp++) {
                float bm = -3e38f;
                #pragma unroll
                for (int nf = 0; nf < 16; nf++)
                    #pragma unroll
                    for (int e = 0; e < 2; e++) {
                        int n = hbase + wn * 128 + nf * 8 + q * 2 + e;
                        float m = acc[(mf * 16 + nf) * 4 + rp * 2 + e] - cchs[n];
                        acc[(mf * 16 + nf) * 4 + rp * 2 + e] = m;   // keep m, not dot
                        if (m > bm) bm = m;
                    }
                tmax[mf][rp] = bm;
            }
        #pragma unroll
        for (int mf = 0; mf < 2; mf++)
            #pragma unroll
            for (int rp = 0; rp < 2; rp++) {
                float v = tmax[mf][rp];
                #pragma unroll
                for (int off = 1; off <= 2; off <<= 1)
                    v = fmaxf(v, __shfl_xor_sync(0xffffffffu, v, off));
                if (q == 0) {
                    int rloc = wm * 32 + mf * 16 + rp * 8 + g;
                    redv[rloc * 2 + wn] = v;
                }
            }
        __syncthreads();
        if (wn == 0 && q == 0) {
            #pragma unroll
            for (int mf = 0; mf < 2; mf++)
                #pragma unroll
                for (int rp = 0; rp < 2; rp++) {
                    int rloc = wm * 32 + mf * 16 + rp * 8 + g;
                    srmax[h * 128 + rloc] = fmaxf(redv[rloc * 2], redv[rloc * 2 + 1]);
                }
        }
        __syncthreads();

        // ---- candidate scan ----
        #pragma unroll
        for (int mf = 0; mf < 2; mf++)
            #pragma unroll
            for (int rp = 0; rp < 2; rp++) {
                int rloc = wm * 32 + mf * 16 + rp * 8 + g;
                float thr = srmax[h * 128 + rloc] - BAND;
                #pragma unroll
                for (int nf = 0; nf < 16; nf++)
                    #pragma unroll
                    for (int e = 0; e < 2; e++) {
                        float m = acc[(mf * 16 + nf) * 4 + rp * 2 + e];
                        if (m >= thr) {
                            int n = hbase + wn * 128 + nf * 8 + q * 2 + e;
                            int slot = atomicAdd(&scnt[rloc], 1);
                            if (slot < CAP) {
                                candk[rloc * CAP + slot] = n;
                                candm[rloc * CAP + slot] = m;
                            }
                        }
                    }
            }
        __syncthreads();
    }

    // ---- exact fp32 rescore: warp wid handles rows wid*16..wid*16+15 ----
    for (int rr = 0; rr < 16; rr++) {
        int rloc = wid * 16 + rr;
        int gi = i0 + rloc;
        if (gi >= N_PTS) continue;

        float xr[8];
        {
            const float4* xp = (const float4*)(x + (size_t)gi * D_DIM + lane * 8);
            float4 v0 = xp[0], v1 = xp[1];
            xr[0] = v0.x; xr[1] = v0.y; xr[2] = v0.z; xr[3] = v0.w;
            xr[4] = v1.x; xr[5] = v1.y; xr[6] = v1.z; xr[7] = v1.w;
        }
        float rmax = fmaxf(srmax[rloc], srmax[128 + rloc]);
        int cnt = scnt[rloc];
        float bv = -3e38f; int bi = 0;

        if (cnt > CAP) {
            for (int k = 0; k < K_C; k++) {
                const float4* cp = (const float4*)(cfp + (size_t)k * D_DIM + lane * 8);
                float4 c0 = cp[0], c1 = cp[1];
                float d = xr[0]*c0.x + xr[1]*c0.y + xr[2]*c0.z + xr[3]*c0.w
                        + xr[4]*c1.x + xr[5]*c1.y + xr[6]*c1.z + xr[7]*c1.w;
                float m = warp_sum(d) - cchs[k];
                if (m > bv || (m == bv && k < bi)) { bv = m; bi = k; }
            }
        } else {
            for (int j = 0; j < cnt; j++) {
                if (candm[rloc * CAP + j] < rmax - BAND) continue;
                int k = candk[rloc * CAP + j];
                const float4* cp = (const float4*)(cfp + (size_t)k * D_DIM + lane * 8);
                float4 c0 = cp[0], c1 = cp[1];
                float d = xr[0]*c0.x + xr[1]*c0.y + xr[2]*c0.z + xr[3]*c0.w
                        + xr[4]*c1.x + xr[5]*c1.y + xr[6]*c1.z + xr[7]*c1.w;
                float m = warp_sum(d) - cchs[k];
                if (m > bv || (m == bv && k < bi)) { bv = m; bi = k; }
            }
        }

        if (PASS == 1) {
            int pv = get_prev(prev, gi);
            const float4* cp = (const float4*)(cfp + (size_t)pv * D_DIM + lane * 8);
            float4 c0 = cp[0], c1 = cp[1];
            float d = xr[0]*c0.x + xr[1]*c0.y + xr[2]*c0.z + xr[3]*c0.w
                    + xr[4]*c1.x + xr[5]*c1.y + xr[6]*c1.z + xr[7]*c1.w;
            float mprev = warp_sum(d) - cchs[pv];
            if (lane == 0) {
                g_assign1[gi] = bi;
                if (mprev < bv - EPS_M) g_match = 0;
            }
        } else {
            if (lane == 0) out[gi] = (float)(g_match ? bi : g_assign1[gi]);
        }
    }
}

// ---------------- launch ----------------
extern "C" void kernel_launch(void* const* d_in, const int* in_sizes, int n_in,
                              void* d_out, int out_size) {
    const float* x     = (const float*)d_in[0];
    const float* cents = (const float*)d_in[1];
    const void*  prev  = d_in[2];
    float* out = (float*)d_out;

    cudaFuncSetAttribute(mma_pass_kernel<1>,
                         cudaFuncAttributeMaxDynamicSharedMemorySize, SM_TOT);
    cudaFuncSetAttribute(mma_pass_kernel<2>,
                         cudaFuncAttributeMaxDynamicSharedMemorySize, SM_TOT);

    init_kernel<<<K_C, 256>>>(cents, prev);
    xcat_kernel<<<(N_PAD * 64) / 256, 256>>>(x);
    count_kernel<<<(N_PTS + 1023) / 1024, 256>>>(prev);
    prefix_kernel<<<1, 512>>>();
    scatteridx_kernel<<<(N_PTS + 255) / 256, 256>>>(prev);
    sum_kernel<<<K_C, 256>>>(x);
    mma_pass_kernel<1><<<N_PAD / MT, 256, SM_TOT>>>(x, cents, prev, out);
    finalize_kernel<<<K_C, 256>>>(cents, out);
    mma_pass_kernel<2><<<N_PAD / MT, 256, SM_TOT>>>(x, cents, prev, out);
}